// round 3
// baseline (speedup 1.0000x reference)
#include <cuda_runtime.h>
#include <cuda_fp16.h>
#include <cstdint>

// Problem dims
#define BB 512
#define SS 512
#define II 256
#define HH 512
#define OO 256
#define G4 2048   // 4*HH, gate-interleaved: n = j*4 + gate, gate order (g,i,f,o)

// GEMM tile config
#define BM 64
#define BN 128
#define BK 32
#define NTHREADS 256
#define NCTA2 128   // (512/64) * (2048/128)

// ---------------- device-global scratch (no cudaMalloc allowed) ----------------
// NOTE: total static device memory must stay well under 2 GB or the host link
// fails with GOTPCREL relocation overflow (seen in R2). XP is fp16: exactly 1 GB.
__device__ float  g_W4x[(size_t)G4 * II];       // [n][k], tf32-rounded
__device__ float  g_W4h[(size_t)G4 * HH];       // [n][k], tf32-rounded
__device__ float  g_bias4[G4];                  // bx + bh combined
__device__ float  g_Wp[(size_t)OO * HH];        // tf32-rounded
__device__ __half g_XP[(size_t)SS * BB * G4];   // x-projections + bias, fp16 (1 GB)
__device__ float  g_H[2][(size_t)BB * HH];      // double-buffered hidden state
__device__ float  g_C[(size_t)BB * HH];         // cell state
__device__ volatile unsigned g_flags[NCTA2];
__device__ volatile unsigned g_gen;

// ---------------- helpers ----------------
__device__ __forceinline__ float tf32r(float x) {
    unsigned u;
    asm("cvt.rna.tf32.f32 %0, %1;" : "=r"(u) : "f"(x));
    return __uint_as_float(u);
}
__device__ __forceinline__ unsigned f2u(float f) { return __float_as_uint(f); }

__device__ __forceinline__ float sigf(float x) {
    return __fdividef(1.f, 1.f + __expf(-x));
}
__device__ __forceinline__ float tanhfast(float x) {
    x = fminf(15.f, fmaxf(-15.f, x));
    float t = __expf(2.f * x);
    return __fdividef(t - 1.f, t + 1.f);
}

// Grid barrier: per-CTA flag slots + generation publish. Targets are monotonic
// across graph replays (base read from g_gen at kernel start), so no reset race.
__device__ __forceinline__ void gridbar(unsigned target) {
    __threadfence();
    __syncthreads();
    if (threadIdx.x == 0) g_flags[blockIdx.x] = target;
    if (blockIdx.x == 0) {
        if (threadIdx.x < NCTA2) {
            while ((int)(g_flags[threadIdx.x] - target) < 0) __nanosleep(20);
        }
        __syncthreads();
        __threadfence();
        if (threadIdx.x == 0) g_gen = target;
        __syncthreads();
    } else {
        if (threadIdx.x == 0) {
            while ((int)(g_gen - target) < 0) __nanosleep(20);
            __threadfence();
        }
        __syncthreads();
    }
}

// ---------------- CTA-level GEMM: C[64x128] += A[64xK] * B[128xK]^T ----------------
// A, B stored K-contiguous (row stride given). tf32 mma.sync m16n8k8, fp32 accum.
// smem: sA 64x36, sB 128x36 (padded rows for conflict-free fragment loads).
// Single smem buffer, register prefetch of the next K-slice overlaps gmem latency.
template <int KTOT>
__device__ __forceinline__ void cta_gemm(
    const float* __restrict__ Abase, int Astride,
    const float* __restrict__ Bbase, int Bstride,
    float* sA, float* sB, float (&acc)[2][4][4])
{
    const int tid  = threadIdx.x;
    const int lane = tid & 31;
    const int warp = tid >> 5;
    const int m0 = (warp >> 2) * 32;  // warp row tile
    const int n0 = (warp & 3) * 32;   // warp col tile
    const int gq = lane >> 2;
    const int t4 = lane & 3;

    __syncthreads();  // smem may be in use by caller's previous phase

    float4 pa[2], pb[4];
    // initial tile -> regs
#pragma unroll
    for (int i = 0; i < 2; i++) {
        int id = tid + i * 256; int row = id >> 3; int kc = (id & 7) << 2;
        pa[i] = *reinterpret_cast<const float4*>(Abase + (size_t)row * Astride + kc);
    }
#pragma unroll
    for (int i = 0; i < 4; i++) {
        int id = tid + i * 256; int row = id >> 3; int kc = (id & 7) << 2;
        pb[i] = *reinterpret_cast<const float4*>(Bbase + (size_t)row * Bstride + kc);
    }
    // regs -> smem (tf32 rounding)
#pragma unroll
    for (int i = 0; i < 2; i++) {
        int id = tid + i * 256; int row = id >> 3; int kc = (id & 7) << 2;
        float4 v = pa[i];
        v.x = tf32r(v.x); v.y = tf32r(v.y); v.z = tf32r(v.z); v.w = tf32r(v.w);
        *reinterpret_cast<float4*>(sA + row * 36 + kc) = v;
    }
#pragma unroll
    for (int i = 0; i < 4; i++) {
        int id = tid + i * 256; int row = id >> 3; int kc = (id & 7) << 2;
        float4 v = pb[i];
        v.x = tf32r(v.x); v.y = tf32r(v.y); v.z = tf32r(v.z); v.w = tf32r(v.w);
        *reinterpret_cast<float4*>(sB + row * 36 + kc) = v;
    }
    __syncthreads();

    for (int k0 = 0; k0 < KTOT; k0 += BK) {
        const bool more = (k0 + BK) < KTOT;
        if (more) {  // prefetch next K-slice into regs (overlaps with mma below)
#pragma unroll
            for (int i = 0; i < 2; i++) {
                int id = tid + i * 256; int row = id >> 3; int kc = (id & 7) << 2;
                pa[i] = *reinterpret_cast<const float4*>(Abase + (size_t)row * Astride + k0 + BK + kc);
            }
#pragma unroll
            for (int i = 0; i < 4; i++) {
                int id = tid + i * 256; int row = id >> 3; int kc = (id & 7) << 2;
                pb[i] = *reinterpret_cast<const float4*>(Bbase + (size_t)row * Bstride + k0 + BK + kc);
            }
        }
#pragma unroll
        for (int kk = 0; kk < BK; kk += 8) {
            unsigned af[2][4], bf[4][2];
#pragma unroll
            for (int mi = 0; mi < 2; mi++) {
                int rb = m0 + mi * 16;
                af[mi][0] = f2u(sA[(rb + gq) * 36 + kk + t4]);
                af[mi][1] = f2u(sA[(rb + 8 + gq) * 36 + kk + t4]);
                af[mi][2] = f2u(sA[(rb + gq) * 36 + kk + t4 + 4]);
                af[mi][3] = f2u(sA[(rb + 8 + gq) * 36 + kk + t4 + 4]);
            }
#pragma unroll
            for (int ni = 0; ni < 4; ni++) {
                int cb = n0 + ni * 8;
                bf[ni][0] = f2u(sB[(cb + gq) * 36 + kk + t4]);
                bf[ni][1] = f2u(sB[(cb + gq) * 36 + kk + t4 + 4]);
            }
#pragma unroll
            for (int mi = 0; mi < 2; mi++) {
#pragma unroll
                for (int ni = 0; ni < 4; ni++) {
                    asm volatile(
                        "mma.sync.aligned.m16n8k8.row.col.f32.tf32.tf32.f32 "
                        "{%0,%1,%2,%3}, {%4,%5,%6,%7}, {%8,%9}, {%0,%1,%2,%3};\n"
                        : "+f"(acc[mi][ni][0]), "+f"(acc[mi][ni][1]),
                          "+f"(acc[mi][ni][2]), "+f"(acc[mi][ni][3])
                        : "r"(af[mi][0]), "r"(af[mi][1]), "r"(af[mi][2]), "r"(af[mi][3]),
                          "r"(bf[ni][0]), "r"(bf[ni][1]));
                }
            }
        }
        if (more) {
            __syncthreads();
#pragma unroll
            for (int i = 0; i < 2; i++) {
                int id = tid + i * 256; int row = id >> 3; int kc = (id & 7) << 2;
                float4 v = pa[i];
                v.x = tf32r(v.x); v.y = tf32r(v.y); v.z = tf32r(v.z); v.w = tf32r(v.w);
                *reinterpret_cast<float4*>(sA + row * 36 + kc) = v;
            }
#pragma unroll
            for (int i = 0; i < 4; i++) {
                int id = tid + i * 256; int row = id >> 3; int kc = (id & 7) << 2;
                float4 v = pb[i];
                v.x = tf32r(v.x); v.y = tf32r(v.y); v.z = tf32r(v.z); v.w = tf32r(v.w);
                *reinterpret_cast<float4*>(sB + row * 36 + kc) = v;
            }
            __syncthreads();
        }
    }
}

// ---------------- kernel 1: pack weights (gate-interleaved, tf32-rounded) ----------------
__global__ void pack_kernel(
    const float* __restrict__ Wgx, const float* __restrict__ Wgh,
    const float* __restrict__ Wix, const float* __restrict__ Wih,
    const float* __restrict__ Wfx, const float* __restrict__ Wfh,
    const float* __restrict__ Wox, const float* __restrict__ Woh,
    const float* __restrict__ bgx, const float* __restrict__ bgh,
    const float* __restrict__ bix, const float* __restrict__ bih,
    const float* __restrict__ bfx, const float* __restrict__ bfh,
    const float* __restrict__ box_, const float* __restrict__ boh,
    const float* __restrict__ Wph)
{
    int idx = blockIdx.x * blockDim.x + threadIdx.x;  // grid covers G4*HH exactly
    if (idx < G4 * HH) {
        int n = idx >> 9, k = idx & 511;
        int gate = n & 3, j = n >> 2;
        const float* W = (gate == 0) ? Wgh : (gate == 1) ? Wih : (gate == 2) ? Wfh : Woh;
        g_W4h[idx] = tf32r(W[j * HH + k]);
    }
    if (idx < G4 * II) {
        int n = idx >> 8, k = idx & 255;
        int gate = n & 3, j = n >> 2;
        const float* W = (gate == 0) ? Wgx : (gate == 1) ? Wix : (gate == 2) ? Wfx : Wox;
        g_W4x[idx] = tf32r(W[j * II + k]);
    }
    if (idx < G4) {
        int gate = idx & 3, j = idx >> 2;
        const float* bx = (gate == 0) ? bgx : (gate == 1) ? bix : (gate == 2) ? bfx : box_;
        const float* bh = (gate == 0) ? bgh : (gate == 1) ? bih : (gate == 2) ? bfh : boh;
        g_bias4[idx] = bx[j] + bh[j];
    }
    if (idx < OO * HH) {
        g_Wp[idx] = tf32r(Wph[idx]);
    }
}

// ---------------- kernel 2: x-projections for all timesteps ----------------
// XP[s][b][n] = fp16( sum_i x[b,s,i] * W4x[n][i] + bias4[n] )
__global__ void __launch_bounds__(NTHREADS) xproj_kernel(const float* __restrict__ x) {
    __shared__ __align__(16) float smem[64 * 132];  // GEMM region uses 6912 of 8448 floats
    float* sA = smem;
    float* sB = smem + 64 * 36;

    const int nt = blockIdx.x;         // 0..15
    const int mt = blockIdx.y;         // 0..4095
    const int s  = mt >> 3;
    const int b0 = (mt & 7) * 64;
    const int n0 = nt * 128;

    float acc[2][4][4];
#pragma unroll
    for (int a = 0; a < 2; a++)
#pragma unroll
        for (int b = 0; b < 4; b++)
#pragma unroll
            for (int c = 0; c < 4; c++) acc[a][b][c] = 0.f;

    const float* Abase = x + ((size_t)b0 * SS + s) * II;  // x[b][s][:] rows
    const float* Bbase = g_W4x + (size_t)n0 * II;
    cta_gemm<II>(Abase, SS * II, Bbase, II, sA, sB, acc);

    __half* XPb = g_XP + (size_t)s * BB * G4;
    const int lane = threadIdx.x & 31, warp = threadIdx.x >> 5;
    const int wm = warp >> 2, wn = warp & 3, gq = lane >> 2, t4 = lane & 3;
#pragma unroll
    for (int mi = 0; mi < 2; mi++) {
#pragma unroll
        for (int ni = 0; ni < 4; ni++) {
            int r = wm * 32 + mi * 16 + gq;
            int c = wn * 32 + ni * 8 + t4 * 2;
            float bv0 = g_bias4[n0 + c], bv1 = g_bias4[n0 + c + 1];
            size_t i0 = (size_t)(b0 + r) * G4 + n0 + c;
            *reinterpret_cast<__half2*>(XPb + i0) =
                __floats2half2_rn(acc[mi][ni][0] + bv0, acc[mi][ni][1] + bv1);
            size_t i1 = (size_t)(b0 + r + 8) * G4 + n0 + c;
            *reinterpret_cast<__half2*>(XPb + i1) =
                __floats2half2_rn(acc[mi][ni][2] + bv0, acc[mi][ni][3] + bv1);
        }
    }
}

// ---------------- kernel 3: persistent recurrent loop + final projection ----------------
__global__ void __launch_bounds__(NTHREADS) lstm_kernel(const float* __restrict__ bph,
                                                        float* __restrict__ out) {
    __shared__ __align__(16) float smem[64 * 132];  // GEMM: 6912 floats; staging: 64x132
    float* sA = smem;
    float* sB = smem + 64 * 36;

    const int tid = threadIdx.x;
    const int cta = blockIdx.x;
    const int bt = cta >> 4;    // 0..7
    const int nt = cta & 15;    // 0..15
    const int b0 = bt * 64;
    const int n0 = nt * 128;

    const unsigned base_gen = g_gen;  // monotonic base across graph replays

    const int lane = tid & 31, warp = tid >> 5;
    const int wm = warp >> 2, wn = warp & 3, gq = lane >> 2, t4 = lane & 3;

    for (int s = 0; s < SS; ++s) {
        const __half* XPb = g_XP + (size_t)s * BB * G4;
        // L2 prefetch of this step's XP tile (64 rows x 256B)
        {
            int row = tid >> 2, seg = tid & 3;
            const __half* p = XPb + (size_t)(b0 + row) * G4 + n0 + seg * 32;
            asm volatile("prefetch.global.L2 [%0];" :: "l"(p));
        }

        float acc[2][4][4];
#pragma unroll
        for (int a = 0; a < 2; a++)
#pragma unroll
            for (int b = 0; b < 4; b++)
#pragma unroll
                for (int c = 0; c < 4; c++) acc[a][b][c] = 0.f;

        if (s > 0) {
            cta_gemm<HH>(g_H[s & 1] + (size_t)b0 * HH, HH,
                         g_W4h + (size_t)n0 * HH, HH, sA, sB, acc);
        }

        // stage acc + XP (bias already folded in) to smem, rows padded to 132
        __syncthreads();
#pragma unroll
        for (int mi = 0; mi < 2; mi++) {
#pragma unroll
            for (int ni = 0; ni < 4; ni++) {
                int r = wm * 32 + mi * 16 + gq;
                int c = wn * 32 + ni * 8 + t4 * 2;
                size_t xi = (size_t)(b0 + r) * G4 + n0 + c;
                float2 x0 = __half22float2(*reinterpret_cast<const __half2*>(XPb + xi));
                smem[r * 132 + c]     = acc[mi][ni][0] + x0.x;
                smem[r * 132 + c + 1] = acc[mi][ni][1] + x0.y;
                size_t xj = (size_t)(b0 + r + 8) * G4 + n0 + c;
                float2 x1 = __half22float2(*reinterpret_cast<const __half2*>(XPb + xj));
                smem[(r + 8) * 132 + c]     = acc[mi][ni][2] + x1.x;
                smem[(r + 8) * 132 + c + 1] = acc[mi][ni][3] + x1.y;
            }
        }
        __syncthreads();

        // gate update: 64 b-rows x 32 j-cols per CTA, 8 (b,j) pairs per thread
#pragma unroll
        for (int q = 0; q < 8; q++) {
            int pi = q * 256 + tid;
            int bl = pi >> 5;   // 0..63
            int jl = pi & 31;   // 0..31
            float4 v = *reinterpret_cast<float4*>(smem + bl * 132 + jl * 4);
            float gg = tanhfast(v.x);
            float iv = sigf(v.y);
            float fv = sigf(v.z);
            float ov = sigf(v.w);
            int bg = b0 + bl;
            int jg = nt * 32 + jl;
            float cold = (s == 0) ? 0.f : g_C[(size_t)bg * HH + jg];
            float cnew = gg * iv + cold * fv;
            float hnew = tanhfast(cnew) * ov;
            g_C[(size_t)bg * HH + jg] = cnew;
            g_H[(s + 1) & 1][(size_t)bg * HH + jg] = hnew;
        }

        gridbar(base_gen + (unsigned)s + 1u);
    }

    // final projection: out[b][o] = h @ Wph^T + bph, h in g_H[0] (512 steps -> buf 0)
    if (cta < 16) {
        const int pb0 = (cta >> 1) * 64;
        const int pn0 = (cta & 1) * 128;
        float acc[2][4][4];
#pragma unroll
        for (int a = 0; a < 2; a++)
#pragma unroll
            for (int b = 0; b < 4; b++)
#pragma unroll
                for (int c = 0; c < 4; c++) acc[a][b][c] = 0.f;
        cta_gemm<HH>(g_H[0] + (size_t)pb0 * HH, HH,
                     g_Wp + (size_t)pn0 * HH, HH, sA, sB, acc);
#pragma unroll
        for (int mi = 0; mi < 2; mi++) {
#pragma unroll
            for (int ni = 0; ni < 4; ni++) {
                int r = wm * 32 + mi * 16 + gq;
                int c = wn * 32 + ni * 8 + t4 * 2;
                float bv0 = bph[pn0 + c], bv1 = bph[pn0 + c + 1];
                out[(size_t)(pb0 + r) * OO + pn0 + c]     = acc[mi][ni][0] + bv0;
                out[(size_t)(pb0 + r) * OO + pn0 + c + 1] = acc[mi][ni][1] + bv1;
                out[(size_t)(pb0 + r + 8) * OO + pn0 + c]     = acc[mi][ni][2] + bv0;
                out[(size_t)(pb0 + r + 8) * OO + pn0 + c + 1] = acc[mi][ni][3] + bv1;
            }
        }
    }
}

// ---------------- launch ----------------
extern "C" void kernel_launch(void* const* d_in, const int* in_sizes, int n_in,
                              void* d_out, int out_size) {
    (void)in_sizes; (void)n_in; (void)out_size;
    const float* x   = (const float*)d_in[0];
    const float* Wgx = (const float*)d_in[1];
    const float* bgx = (const float*)d_in[2];
    const float* Wgh = (const float*)d_in[3];
    const float* bgh = (const float*)d_in[4];
    const float* Wix = (const float*)d_in[5];
    const float* bix = (const float*)d_in[6];
    const float* Wih = (const float*)d_in[7];
    const float* bih = (const float*)d_in[8];
    const float* Wfx = (const float*)d_in[9];
    const float* bfx = (const float*)d_in[10];
    const float* Wfh = (const float*)d_in[11];
    const float* bfh = (const float*)d_in[12];
    const float* Wox = (const float*)d_in[13];
    const float* box_ = (const float*)d_in[14];
    const float* Woh = (const float*)d_in[15];
    const float* boh = (const float*)d_in[16];
    const float* Wph = (const float*)d_in[17];
    const float* bph = (const float*)d_in[18];

    pack_kernel<<<(G4 * HH) / NTHREADS, NTHREADS>>>(
        Wgx, Wgh, Wix, Wih, Wfx, Wfh, Wox, Woh,
        bgx, bgh, bix, bih, bfx, bfh, box_, boh, Wph);

    dim3 g1(16, (SS * BB) / BM);  // 16 x 4096 tiles
    xproj_kernel<<<g1, NTHREADS>>>(x);

    lstm_kernel<<<NCTA2, NTHREADS>>>(bph, (float*)d_out);
}

// round 4
// speedup vs baseline: 2.0182x; 2.0182x over previous
#include <cuda_runtime.h>
#include <cuda_fp16.h>
#include <cstdint>

// Problem dims
#define BB 512
#define SS 512
#define II 256
#define HH 512
#define OO 256
#define G4 2048   // 4*HH, gate-interleaved: n = j*4 + gate, order (g,i,f,o)

#define NTHREADS 256
#define NCTA2 128   // 8 b-tiles(64) x 16 n-tiles(128)

// SMEM geometry
#define LSTM_SMEM  ((128 + 64) * 520 * 2)   // 199,680 B: sW 128x520 halfs + sA 64x520 halfs
#define XPROJ_SMEM ((64 + 128) * 264 * 2)   // 101,376 B: sA 64x264 + sB 128x264 halfs

// ---------------- device-global scratch (no cudaMalloc allowed) ----------------
// Keep total statics well under ~2 GB (R2 link failure). ~1.16 GB here.
__device__ __align__(16) __half g_W4x_h[(size_t)G4 * II];   // [n][k] fp16
__device__ __align__(16) __half g_W4h_h[(size_t)G4 * HH];   // [n][k] fp16
__device__ __align__(16) __half g_Wp_h[(size_t)OO * HH];    // fp16
__device__ float  g_bias4[G4];                              // bx + bh
__device__ __align__(16) __half g_Xh[(size_t)BB * SS * II]; // x in fp16 (128 MB)
__device__ __align__(16) __half g_XP[(size_t)SS * BB * G4]; // x-projections + bias (1 GB)
__device__ __align__(16) __half g_Hh[2][(size_t)BB * HH];   // double-buffered h, fp16
__device__ float  g_C[(size_t)BB * HH];                     // cell state fp32
__device__ unsigned g_arrive;                               // grid-barrier counter

// ---------------- helpers ----------------
__device__ __forceinline__ float sigf(float x) {
    return __fdividef(1.f, 1.f + __expf(-x));
}
__device__ __forceinline__ float tanhfast(float x) {
    x = fminf(15.f, fmaxf(-15.f, x));
    float t = __expf(2.f * x);
    return __fdividef(t - 1.f, t + 1.f);
}

__device__ __forceinline__ void ldsm4(uint32_t* r, uint32_t addr) {
    asm volatile("ldmatrix.sync.aligned.m8n8.x4.shared.b16 {%0,%1,%2,%3}, [%4];"
                 : "=r"(r[0]), "=r"(r[1]), "=r"(r[2]), "=r"(r[3]) : "r"(addr));
}
__device__ __forceinline__ void mma16816(float* d, const uint32_t* a, const uint32_t* b) {
    asm volatile("mma.sync.aligned.m16n8k16.row.col.f32.f16.f16.f32 "
                 "{%0,%1,%2,%3},{%4,%5,%6,%7},{%8,%9},{%0,%1,%2,%3};"
                 : "+f"(d[0]), "+f"(d[1]), "+f"(d[2]), "+f"(d[3])
                 : "r"(a[0]), "r"(a[1]), "r"(a[2]), "r"(a[3]), "r"(b[0]), "r"(b[1]));
}

// Single-counter grid barrier. g_arrive is zeroed by pack_kernel each launch
// (stream order guarantees the previous lstm_kernel fully retired first).
__device__ __forceinline__ void gridbar(unsigned target) {
    __syncthreads();
    if (threadIdx.x == 0) {
        __threadfence();
        unsigned* p = &g_arrive;
        asm volatile("red.relaxed.gpu.global.add.u32 [%0], 1;" :: "l"(p) : "memory");
        unsigned v;
        while (true) {
            asm volatile("ld.acquire.gpu.global.u32 %0, [%1];" : "=r"(v) : "l"(p) : "memory");
            if ((int)(v - target) >= 0) break;
            __nanosleep(64);
        }
    }
    __syncthreads();
}

// ---------------- kernel 1: pack weights fp16 gate-interleaved + reset barrier ----------------
__global__ void pack_kernel(
    const float* __restrict__ Wgx, const float* __restrict__ Wgh,
    const float* __restrict__ Wix, const float* __restrict__ Wih,
    const float* __restrict__ Wfx, const float* __restrict__ Wfh,
    const float* __restrict__ Wox, const float* __restrict__ Woh,
    const float* __restrict__ bgx, const float* __restrict__ bgh,
    const float* __restrict__ bix, const float* __restrict__ bih,
    const float* __restrict__ bfx, const float* __restrict__ bfh,
    const float* __restrict__ box_, const float* __restrict__ boh,
    const float* __restrict__ Wph)
{
    int idx = blockIdx.x * blockDim.x + threadIdx.x;  // covers G4*HH = 1,048,576 exactly
    if (idx == 0) g_arrive = 0;
    if (idx < G4 * HH) {
        int n = idx >> 9, k = idx & 511;
        int gate = n & 3, j = n >> 2;
        const float* W = (gate == 0) ? Wgh : (gate == 1) ? Wih : (gate == 2) ? Wfh : Woh;
        g_W4h_h[idx] = __float2half_rn(W[j * HH + k]);
    }
    if (idx < G4 * II) {
        int n = idx >> 8, k = idx & 255;
        int gate = n & 3, j = n >> 2;
        const float* W = (gate == 0) ? Wgx : (gate == 1) ? Wix : (gate == 2) ? Wfx : Wox;
        g_W4x_h[idx] = __float2half_rn(W[j * II + k]);
    }
    if (idx < G4) {
        int gate = idx & 3, j = idx >> 2;
        const float* bx = (gate == 0) ? bgx : (gate == 1) ? bix : (gate == 2) ? bfx : box_;
        const float* bh = (gate == 0) ? bgh : (gate == 1) ? bih : (gate == 2) ? bfh : boh;
        g_bias4[idx] = bx[j] + bh[j];
    }
    if (idx < OO * HH) {
        g_Wp_h[idx] = __float2half_rn(Wph[idx]);
    }
}

// ---------------- kernel 1b: convert x to fp16 ----------------
__global__ void xconv_kernel(const float* __restrict__ x) {
    size_t i = ((size_t)blockIdx.x * NTHREADS + threadIdx.x) * 8;
    float4 a = *reinterpret_cast<const float4*>(x + i);
    float4 b = *reinterpret_cast<const float4*>(x + i + 4);
    __half2 h0 = __floats2half2_rn(a.x, a.y);
    __half2 h1 = __floats2half2_rn(a.z, a.w);
    __half2 h2 = __floats2half2_rn(b.x, b.y);
    __half2 h3 = __floats2half2_rn(b.z, b.w);
    uint4 o;
    o.x = *reinterpret_cast<uint32_t*>(&h0);
    o.y = *reinterpret_cast<uint32_t*>(&h1);
    o.z = *reinterpret_cast<uint32_t*>(&h2);
    o.w = *reinterpret_cast<uint32_t*>(&h3);
    *reinterpret_cast<uint4*>(g_Xh + i) = o;
}

// ---------------- kernel 2: x-projections, fp16 mma ----------------
// XP[s][b][n] = fp16( sum_i x[b,s,i] * W4x[n][i] + bias4[n] )
__global__ void __launch_bounds__(NTHREADS) xproj_kernel() {
    extern __shared__ __align__(16) char dsm[];
    __half* sA = (__half*)dsm;                   // 64 x 264
    __half* sB = (__half*)(dsm + 64 * 264 * 2);  // 128 x 264

    const int tid = threadIdx.x;
    const int nt = blockIdx.x;         // 0..15
    const int mt = blockIdx.y;         // 0..4095
    const int s  = mt >> 3;
    const int b0 = (mt & 7) * 64;
    const int n0 = nt * 128;

    // load A (x tile, 64x256 halfs) and B (W4x tile, 128x256 halfs)
#pragma unroll
    for (int i = 0; i < 8; i++) {
        int id = i * 256 + tid; int row = id >> 5; int c8 = (id & 31) * 8;
        *reinterpret_cast<uint4*>(sA + row * 264 + c8) =
            *reinterpret_cast<const uint4*>(g_Xh + ((size_t)(b0 + row) * SS + s) * II + c8);
    }
#pragma unroll
    for (int i = 0; i < 16; i++) {
        int id = i * 256 + tid; int row = id >> 5; int c8 = (id & 31) * 8;
        *reinterpret_cast<uint4*>(sB + row * 264 + c8) =
            *reinterpret_cast<const uint4*>(g_W4x_h + (size_t)(n0 + row) * II + c8);
    }
    __syncthreads();

    const int lane = tid & 31, warp = tid >> 5;
    const int m0w = (warp >> 2) * 32, n0w = (warp & 3) * 32;
    const int grp = lane >> 3, rl = lane & 7;
    const uint32_t sA32 = (uint32_t)__cvta_generic_to_shared(sA);
    const uint32_t sB32 = (uint32_t)__cvta_generic_to_shared(sB);
    uint32_t aAddr[2], bAddr[2];
#pragma unroll
    for (int mi = 0; mi < 2; mi++) {
        int row = m0w + mi * 16 + (grp & 1) * 8 + rl;
        aAddr[mi] = sA32 + (row * 264 + (grp >> 1) * 8) * 2;
    }
#pragma unroll
    for (int nj = 0; nj < 2; nj++) {
        int row = n0w + nj * 16 + (grp >> 1) * 8 + rl;
        bAddr[nj] = sB32 + (row * 264 + (grp & 1) * 8) * 2;
    }

    float acc[2][4][4] = {};
#pragma unroll
    for (int kk = 0; kk < II; kk += 16) {
        uint32_t a[2][4], b[2][4];
        ldsm4(a[0], aAddr[0] + kk * 2);
        ldsm4(a[1], aAddr[1] + kk * 2);
        ldsm4(b[0], bAddr[0] + kk * 2);
        ldsm4(b[1], bAddr[1] + kk * 2);
#pragma unroll
        for (int mi = 0; mi < 2; mi++)
#pragma unroll
            for (int ni = 0; ni < 4; ni++)
                mma16816(acc[mi][ni], a[mi], b[ni >> 1] + (ni & 1) * 2);
    }

    // epilogue: + bias, fp16 store
    const int gq = lane >> 2, t4 = lane & 3;
    __half* XPb = g_XP + (size_t)s * BB * G4;
#pragma unroll
    for (int mi = 0; mi < 2; mi++) {
#pragma unroll
        for (int ni = 0; ni < 4; ni++) {
            int r = m0w + mi * 16 + gq;
            int c = n0w + ni * 8 + t4 * 2;
            float bv0 = g_bias4[n0 + c], bv1 = g_bias4[n0 + c + 1];
            *reinterpret_cast<__half2*>(XPb + (size_t)(b0 + r) * G4 + n0 + c) =
                __floats2half2_rn(acc[mi][ni][0] + bv0, acc[mi][ni][1] + bv1);
            *reinterpret_cast<__half2*>(XPb + (size_t)(b0 + r + 8) * G4 + n0 + c) =
                __floats2half2_rn(acc[mi][ni][2] + bv0, acc[mi][ni][3] + bv1);
        }
    }
}

// ---------------- kernel 3: persistent recurrent loop + final projection ----------------
// 128 CTAs, 1/SM. W4h tile (128x512 fp16 = 128 KB) RESIDENT in smem across all steps.
__global__ void __launch_bounds__(NTHREADS) lstm_kernel(const float* __restrict__ bph,
                                                        float* __restrict__ out) {
    extern __shared__ __align__(16) char dsm[];
    __half* sW = (__half*)dsm;                    // 128 x 520 halfs (resident W tile)
    __half* sA = (__half*)(dsm + 128 * 520 * 2);  // 64 x 520 halfs (h tile / reuse as stage)
    float*  stg = (float*)sA;                     // 64 x 132 floats (33,792 B <= 66,560 B)

    const int tid = threadIdx.x;
    const int cta = blockIdx.x;
    const int bt = cta >> 4;    // 0..7
    const int nt = cta & 15;    // 0..15
    const int b0 = bt * 64;
    const int n0 = nt * 128;

    // load resident W tile once
#pragma unroll
    for (int i = 0; i < 32; i++) {
        int id = i * 256 + tid; int row = id >> 6; int c8 = (id & 63) * 8;
        *reinterpret_cast<uint4*>(sW + row * 520 + c8) =
            *reinterpret_cast<const uint4*>(g_W4h_h + (size_t)(n0 + row) * HH + c8);
    }

    const int lane = tid & 31, warp = tid >> 5;
    const int m0w = (warp >> 2) * 32, n0w = (warp & 3) * 32;
    const int grp = lane >> 3, rl = lane & 7;
    const int gq = lane >> 2, t4 = lane & 3;
    const uint32_t sA32 = (uint32_t)__cvta_generic_to_shared(sA);
    const uint32_t sW32 = (uint32_t)__cvta_generic_to_shared(sW);
    uint32_t aAddr[2], bAddr[2];
#pragma unroll
    for (int mi = 0; mi < 2; mi++) {
        int row = m0w + mi * 16 + (grp & 1) * 8 + rl;
        aAddr[mi] = sA32 + (row * 520 + (grp >> 1) * 8) * 2;
    }
#pragma unroll
    for (int nj = 0; nj < 2; nj++) {
        int row = n0w + nj * 16 + (grp >> 1) * 8 + rl;
        bAddr[nj] = sW32 + (row * 520 + (grp & 1) * 8) * 2;
    }

    for (int s = 0; s < SS; ++s) {
        float acc[2][4][4] = {};

        if (s > 0) {
            // load h tile (64x512 halfs) into sA
            const __half* hsrc = g_Hh[s & 1] + (size_t)b0 * HH;
#pragma unroll
            for (int i = 0; i < 16; i++) {
                int id = i * 256 + tid; int row = id >> 6; int c8 = (id & 63) * 8;
                *reinterpret_cast<uint4*>(sA + row * 520 + c8) =
                    *reinterpret_cast<const uint4*>(hsrc + (size_t)row * HH + c8);
            }
            __syncthreads();

#pragma unroll 4
            for (int kk = 0; kk < HH; kk += 16) {
                uint32_t a[2][4], b[2][4];
                ldsm4(a[0], aAddr[0] + kk * 2);
                ldsm4(a[1], aAddr[1] + kk * 2);
                ldsm4(b[0], bAddr[0] + kk * 2);
                ldsm4(b[1], bAddr[1] + kk * 2);
#pragma unroll
                for (int mi = 0; mi < 2; mi++)
#pragma unroll
                    for (int ni = 0; ni < 4; ni++)
                        mma16816(acc[mi][ni], a[mi], b[ni >> 1] + (ni & 1) * 2);
            }
            __syncthreads();  // GEMM done reading sA; stage will overwrite it
        }

        // stage acc + XP into smem (transpose to (b, j) ownership)
        const __half* XPb = g_XP + (size_t)s * BB * G4;
#pragma unroll
        for (int mi = 0; mi < 2; mi++) {
#pragma unroll
            for (int ni = 0; ni < 4; ni++) {
                int r = m0w + mi * 16 + gq;
                int c = n0w + ni * 8 + t4 * 2;
                float2 x0 = __half22float2(
                    *reinterpret_cast<const __half2*>(XPb + (size_t)(b0 + r) * G4 + n0 + c));
                stg[r * 132 + c]     = acc[mi][ni][0] + x0.x;
                stg[r * 132 + c + 1] = acc[mi][ni][1] + x0.y;
                float2 x1 = __half22float2(
                    *reinterpret_cast<const __half2*>(XPb + (size_t)(b0 + r + 8) * G4 + n0 + c));
                stg[(r + 8) * 132 + c]     = acc[mi][ni][2] + x1.x;
                stg[(r + 8) * 132 + c + 1] = acc[mi][ni][3] + x1.y;
            }
        }
        __syncthreads();

        // gates: 64 b-rows x 32 j-cols per CTA
        __half* hdst = g_Hh[(s + 1) & 1];
#pragma unroll
        for (int q = 0; q < 8; q++) {
            int pi = q * 256 + tid;
            int bl = pi >> 5;
            int jl = pi & 31;
            float4 v = *reinterpret_cast<float4*>(stg + bl * 132 + jl * 4);
            float gg = tanhfast(v.x);
            float iv = sigf(v.y);
            float fv = sigf(v.z);
            float ov = sigf(v.w);
            int bg = b0 + bl;
            int jg = nt * 32 + jl;
            float cold = (s == 0) ? 0.f : g_C[(size_t)bg * HH + jg];
            float cnew = gg * iv + cold * fv;
            float hnew = tanhfast(cnew) * ov;
            g_C[(size_t)bg * HH + jg] = cnew;
            hdst[(size_t)bg * HH + jg] = __float2half_rn(hnew);
        }

        gridbar((unsigned)(s + 1) * NCTA2);
    }

    // final projection: out = h @ Wp^T + bph; final h is in g_Hh[0]
    if (cta < 16) {
        const int pb0 = (cta >> 1) * 64;
        const int pn0 = (cta & 1) * 128;
#pragma unroll
        for (int i = 0; i < 32; i++) {
            int id = i * 256 + tid; int row = id >> 6; int c8 = (id & 63) * 8;
            *reinterpret_cast<uint4*>(sW + row * 520 + c8) =
                *reinterpret_cast<const uint4*>(g_Wp_h + (size_t)(pn0 + row) * HH + c8);
        }
#pragma unroll
        for (int i = 0; i < 16; i++) {
            int id = i * 256 + tid; int row = id >> 6; int c8 = (id & 63) * 8;
            *reinterpret_cast<uint4*>(sA + row * 520 + c8) =
                *reinterpret_cast<const uint4*>(g_Hh[0] + (size_t)(pb0 + row) * HH + c8);
        }
        __syncthreads();

        float acc[2][4][4] = {};
#pragma unroll 4
        for (int kk = 0; kk < HH; kk += 16) {
            uint32_t a[2][4], b[2][4];
            ldsm4(a[0], aAddr[0] + kk * 2);
            ldsm4(a[1], aAddr[1] + kk * 2);
            ldsm4(b[0], bAddr[0] + kk * 2);
            ldsm4(b[1], bAddr[1] + kk * 2);
#pragma unroll
            for (int mi = 0; mi < 2; mi++)
#pragma unroll
                for (int ni = 0; ni < 4; ni++)
                    mma16816(acc[mi][ni], a[mi], b[ni >> 1] + (ni & 1) * 2);
        }
#pragma unroll
        for (int mi = 0; mi < 2; mi++) {
#pragma unroll
            for (int ni = 0; ni < 4; ni++) {
                int r = m0w + mi * 16 + gq;
                int c = n0w + ni * 8 + t4 * 2;
                float bv0 = bph[pn0 + c], bv1 = bph[pn0 + c + 1];
                out[(size_t)(pb0 + r) * OO + pn0 + c]     = acc[mi][ni][0] + bv0;
                out[(size_t)(pb0 + r) * OO + pn0 + c + 1] = acc[mi][ni][1] + bv1;
                out[(size_t)(pb0 + r + 8) * OO + pn0 + c]     = acc[mi][ni][2] + bv0;
                out[(size_t)(pb0 + r + 8) * OO + pn0 + c + 1] = acc[mi][ni][3] + bv1;
            }
        }
    }
}

// ---------------- launch ----------------
extern "C" void kernel_launch(void* const* d_in, const int* in_sizes, int n_in,
                              void* d_out, int out_size) {
    (void)in_sizes; (void)n_in; (void)out_size;
    const float* x   = (const float*)d_in[0];
    const float* Wgx = (const float*)d_in[1];
    const float* bgx = (const float*)d_in[2];
    const float* Wgh = (const float*)d_in[3];
    const float* bgh = (const float*)d_in[4];
    const float* Wix = (const float*)d_in[5];
    const float* bix = (const float*)d_in[6];
    const float* Wih = (const float*)d_in[7];
    const float* bih = (const float*)d_in[8];
    const float* Wfx = (const float*)d_in[9];
    const float* bfx = (const float*)d_in[10];
    const float* Wfh = (const float*)d_in[11];
    const float* bfh = (const float*)d_in[12];
    const float* Wox = (const float*)d_in[13];
    const float* box_ = (const float*)d_in[14];
    const float* Woh = (const float*)d_in[15];
    const float* boh = (const float*)d_in[16];
    const float* Wph = (const float*)d_in[17];
    const float* bph = (const float*)d_in[18];

    cudaFuncSetAttribute((const void*)xproj_kernel,
                         cudaFuncAttributeMaxDynamicSharedMemorySize, XPROJ_SMEM);
    cudaFuncSetAttribute((const void*)lstm_kernel,
                         cudaFuncAttributeMaxDynamicSharedMemorySize, LSTM_SMEM);

    pack_kernel<<<(G4 * HH) / NTHREADS, NTHREADS>>>(
        Wgx, Wgh, Wix, Wih, Wfx, Wfh, Wox, Woh,
        bgx, bgh, bix, bih, bfx, bfh, box_, boh, Wph);

    xconv_kernel<<<(BB * SS * II) / (NTHREADS * 8), NTHREADS>>>(x);

    dim3 g1(16, SS * (BB / 64));  // 16 x 4096 tiles
    xproj_kernel<<<g1, NTHREADS, XPROJ_SMEM>>>();

    lstm_kernel<<<NCTA2, NTHREADS, LSTM_SMEM>>>(bph, (float*)d_out);
}

// round 6
// speedup vs baseline: 2.0858x; 1.0334x over previous
#include <cuda_runtime.h>
#include <cuda_fp16.h>
#include <cstdint>

// Problem dims
#define BB 512
#define SS 512
#define II 256
#define HH 512
#define OO 256
#define G4 2048   // 4*HH, gate-interleaved: n = j*4 + gate, order (g,i,f,o)

#define PTHREADS 256
#define LTHREADS 512
#define NCTA2 128   // 8 bt-groups x 16 nt

// SMEM geometry
#define LSTM_SMEM  ((128 + 64) * 520 * 2)   // 199,680 B: sW 128x520 + sA 64x520 halfs
#define XPROJ_SMEM ((64 + 128) * 264 * 2)   // 101,376 B: 2 CTAs/SM fit (202,752 <= 228KB)

// ---------------- device-global scratch (no cudaMalloc; keep < ~1.5 GB total) ----------------
__device__ __align__(16) __half g_W4x_h[(size_t)G4 * II];
__device__ __align__(16) __half g_W4h_h[(size_t)G4 * HH];
__device__ __align__(16) __half g_Wp_h[(size_t)OO * HH];
__device__ float  g_bias4[G4];
__device__ __align__(16) __half g_Xh[(size_t)BB * SS * II];  // x fp16 (128 MB)
__device__ __align__(16) __half g_XP[(size_t)SS * BB * G4];  // x-projections + bias (1 GB)
__device__ __align__(16) __half g_Hh[2][(size_t)BB * HH];
__device__ float  g_C[(size_t)BB * HH];
__device__ unsigned g_grp[8 * 32];   // per-bt-group barrier counters, 128B apart
__device__ unsigned g_arrive;        // one global barrier before projection

// ---------------- helpers ----------------
__device__ __forceinline__ float sigf(float x) {
    return __fdividef(1.f, 1.f + __expf(-x));
}
__device__ __forceinline__ float tanhfast(float x) {
    x = fminf(15.f, fmaxf(-15.f, x));
    float t = __expf(2.f * x);
    return __fdividef(t - 1.f, t + 1.f);
}
__device__ __forceinline__ void ldsm4(uint32_t* r, uint32_t addr) {
    asm volatile("ldmatrix.sync.aligned.m8n8.x4.shared.b16 {%0,%1,%2,%3}, [%4];"
                 : "=r"(r[0]), "=r"(r[1]), "=r"(r[2]), "=r"(r[3]) : "r"(addr));
}
__device__ __forceinline__ void mma16816(float* d, const uint32_t* a, const uint32_t* b) {
    asm volatile("mma.sync.aligned.m16n8k16.row.col.f32.f16.f16.f32 "
                 "{%0,%1,%2,%3},{%4,%5,%6,%7},{%8,%9},{%0,%1,%2,%3};"
                 : "+f"(d[0]), "+f"(d[1]), "+f"(d[2]), "+f"(d[3])
                 : "r"(a[0]), "r"(a[1]), "r"(a[2]), "r"(a[3]), "r"(b[0]), "r"(b[1]));
}
__device__ __forceinline__ void cpasync16(uint32_t dst, const void* src) {
    asm volatile("cp.async.cg.shared.global [%0], [%1], 16;" :: "r"(dst), "l"(src));
}
__device__ __forceinline__ void cpasync_wait() {
    asm volatile("cp.async.commit_group;\ncp.async.wait_group 0;" ::: "memory");
}

// Barrier: counter zeroed by pack_kernel each launch (stream order makes this safe).
__device__ __forceinline__ void ctr_bar(unsigned* ctr, unsigned target) {
    __syncthreads();
    if (threadIdx.x == 0) {
        __threadfence();
        asm volatile("red.relaxed.gpu.global.add.u32 [%0], 1;" :: "l"(ctr) : "memory");
        unsigned v;
        do {
            asm volatile("ld.acquire.gpu.global.u32 %0, [%1];" : "=r"(v) : "l"(ctr) : "memory");
        } while ((int)(v - target) < 0);
    }
    __syncthreads();
}

// ---------------- kernel 1: pack weights fp16 gate-interleaved + reset barriers ----------------
__global__ void pack_kernel(
    const float* __restrict__ Wgx, const float* __restrict__ Wgh,
    const float* __restrict__ Wix, const float* __restrict__ Wih,
    const float* __restrict__ Wfx, const float* __restrict__ Wfh,
    const float* __restrict__ Wox, const float* __restrict__ Woh,
    const float* __restrict__ bgx, const float* __restrict__ bgh,
    const float* __restrict__ bix, const float* __restrict__ bih,
    const float* __restrict__ bfx, const float* __restrict__ bfh,
    const float* __restrict__ box_, const float* __restrict__ boh,
    const float* __restrict__ Wph)
{
    int idx = blockIdx.x * blockDim.x + threadIdx.x;  // covers G4*HH exactly
    if (idx < 8 * 32) g_grp[idx] = 0;
    if (idx == 0) g_arrive = 0;
    if (idx < G4 * HH) {
        int n = idx >> 9, k = idx & 511;
        int gate = n & 3, j = n >> 2;
        const float* W = (gate == 0) ? Wgh : (gate == 1) ? Wih : (gate == 2) ? Wfh : Woh;
        g_W4h_h[idx] = __float2half_rn(W[j * HH + k]);
    }
    if (idx < G4 * II) {
        int n = idx >> 8, k = idx & 255;
        int gate = n & 3, j = n >> 2;
        const float* W = (gate == 0) ? Wgx : (gate == 1) ? Wix : (gate == 2) ? Wfx : Wox;
        g_W4x_h[idx] = __float2half_rn(W[j * II + k]);
    }
    if (idx < G4) {
        int gate = idx & 3, j = idx >> 2;
        const float* bx = (gate == 0) ? bgx : (gate == 1) ? bix : (gate == 2) ? bfx : box_;
        const float* bh = (gate == 0) ? bgh : (gate == 1) ? bih : (gate == 2) ? bfh : boh;
        g_bias4[idx] = bx[j] + bh[j];
    }
    if (idx < OO * HH) {
        g_Wp_h[idx] = __float2half_rn(Wph[idx]);
    }
}

// ---------------- kernel 1b: convert x to fp16 ----------------
__global__ void xconv_kernel(const float* __restrict__ x) {
    size_t i = ((size_t)blockIdx.x * PTHREADS + threadIdx.x) * 8;
    float4 a = *reinterpret_cast<const float4*>(x + i);
    float4 b = *reinterpret_cast<const float4*>(x + i + 4);
    __half2 h0 = __floats2half2_rn(a.x, a.y);
    __half2 h1 = __floats2half2_rn(a.z, a.w);
    __half2 h2 = __floats2half2_rn(b.x, b.y);
    __half2 h3 = __floats2half2_rn(b.z, b.w);
    uint4 o;
    o.x = *reinterpret_cast<uint32_t*>(&h0);
    o.y = *reinterpret_cast<uint32_t*>(&h1);
    o.z = *reinterpret_cast<uint32_t*>(&h2);
    o.w = *reinterpret_cast<uint32_t*>(&h3);
    *reinterpret_cast<uint4*>(g_Xh + i) = o;
}

// ---------------- kernel 2: x-projections, fp16 mma, 2 CTAs/SM ----------------
__global__ void __launch_bounds__(PTHREADS, 2) xproj_kernel() {
    extern __shared__ __align__(16) char dsm[];
    __half* sA = (__half*)dsm;                   // 64 x 264
    __half* sB = (__half*)(dsm + 64 * 264 * 2);  // 128 x 264

    const int tid = threadIdx.x;
    const int nt = blockIdx.x;         // 0..15
    const int mt = blockIdx.y;         // 0..4095
    const int s  = mt >> 3;
    const int b0 = (mt & 7) * 64;
    const int n0 = nt * 128;

#pragma unroll
    for (int i = 0; i < 8; i++) {
        int id = i * 256 + tid; int row = id >> 5; int c8 = (id & 31) * 8;
        *reinterpret_cast<uint4*>(sA + row * 264 + c8) =
            *reinterpret_cast<const uint4*>(g_Xh + ((size_t)(b0 + row) * SS + s) * II + c8);
    }
#pragma unroll
    for (int i = 0; i < 16; i++) {
        int id = i * 256 + tid; int row = id >> 5; int c8 = (id & 31) * 8;
        *reinterpret_cast<uint4*>(sB + row * 264 + c8) =
            *reinterpret_cast<const uint4*>(g_W4x_h + (size_t)(n0 + row) * II + c8);
    }
    __syncthreads();

    const int lane = tid & 31, warp = tid >> 5;
    const int m0w = (warp >> 2) * 32, n0w = (warp & 3) * 32;
    const int grp = lane >> 3, rl = lane & 7;
    const uint32_t sA32 = (uint32_t)__cvta_generic_to_shared(sA);
    const uint32_t sB32 = (uint32_t)__cvta_generic_to_shared(sB);
    uint32_t aAddr[2], bAddr[2];
#pragma unroll
    for (int mi = 0; mi < 2; mi++) {
        int row = m0w + mi * 16 + (grp & 1) * 8 + rl;
        aAddr[mi] = sA32 + (row * 264 + (grp >> 1) * 8) * 2;
    }
#pragma unroll
    for (int nj = 0; nj < 2; nj++) {
        int row = n0w + nj * 16 + (grp >> 1) * 8 + rl;
        bAddr[nj] = sB32 + (row * 264 + (grp & 1) * 8) * 2;
    }

    float acc[2][4][4] = {};
#pragma unroll
    for (int kk = 0; kk < II; kk += 16) {
        uint32_t a[2][4], b[2][4];
        ldsm4(a[0], aAddr[0] + kk * 2);
        ldsm4(a[1], aAddr[1] + kk * 2);
        ldsm4(b[0], bAddr[0] + kk * 2);
        ldsm4(b[1], bAddr[1] + kk * 2);
#pragma unroll
        for (int mi = 0; mi < 2; mi++)
#pragma unroll
            for (int ni = 0; ni < 4; ni++)
                mma16816(acc[mi][ni], a[mi], b[ni >> 1] + (ni & 1) * 2);
    }

    const int gq = lane >> 2, t4 = lane & 3;
    __half* XPb = g_XP + (size_t)s * BB * G4;
#pragma unroll
    for (int mi = 0; mi < 2; mi++) {
#pragma unroll
        for (int ni = 0; ni < 4; ni++) {
            int r = m0w + mi * 16 + gq;
            int c = n0w + ni * 8 + t4 * 2;
            float bv0 = g_bias4[n0 + c], bv1 = g_bias4[n0 + c + 1];
            *reinterpret_cast<__half2*>(XPb + (size_t)(b0 + r) * G4 + n0 + c) =
                __floats2half2_rn(acc[mi][ni][0] + bv0, acc[mi][ni][1] + bv1);
            *reinterpret_cast<__half2*>(XPb + (size_t)(b0 + r + 8) * G4 + n0 + c) =
                __floats2half2_rn(acc[mi][ni][2] + bv0, acc[mi][ni][3] + bv1);
        }
    }
}

// ---------------- kernel 3: persistent recurrent loop, 512 threads, group barriers ----------------
__global__ void __launch_bounds__(LTHREADS) lstm_kernel(const float* __restrict__ bph,
                                                        float* __restrict__ out) {
    extern __shared__ __align__(16) char dsm[];
    __half* sW = (__half*)dsm;                    // 128 x 520 (resident W tile)
    __half* sA = (__half*)(dsm + 128 * 520 * 2);  // 64 x 520 (h tile / stage)
    float*  stg = (float*)sA;                     // 64 x 132 floats (33,792 B)

    const int tid = threadIdx.x;
    const int cta = blockIdx.x;
    const int bt = cta >> 4;    // 0..7 (group id)
    const int nt = cta & 15;    // 0..15
    const int b0 = bt * 64;
    const int n0 = nt * 128;
    unsigned* grp_ctr = &g_grp[bt * 32];

    const uint32_t sA32 = (uint32_t)__cvta_generic_to_shared(sA);
    const uint32_t sW32 = (uint32_t)__cvta_generic_to_shared(sW);

    // resident W tile: 128 rows x 512 halves = 8192 uint4, 16 per thread
#pragma unroll
    for (int i = 0; i < 16; i++) {
        int id = i * 512 + tid; int row = id >> 6; int c8 = (id & 63) * 8;
        cpasync16(sW32 + (row * 520 + c8) * 2,
                  g_W4h_h + (size_t)(n0 + row) * HH + c8);
    }
    cpasync_wait();

    const int lane = tid & 31, warp = tid >> 5;
    const int m0w = (warp >> 2) * 16;   // 4x4 warp grid: rows 16, cols 32
    const int n0w = (warp & 3) * 32;
    const int grp = lane >> 3, rl = lane & 7;
    const int gq = lane >> 2, t4 = lane & 3;
    const uint32_t aAddr = sA32 + ((m0w + (grp & 1) * 8 + rl) * 520 + (grp >> 1) * 8) * 2;
    uint32_t bAddr[2];
#pragma unroll
    for (int nj = 0; nj < 2; nj++) {
        int row = n0w + nj * 16 + (grp >> 1) * 8 + rl;
        bAddr[nj] = sW32 + (row * 520 + (grp & 1) * 8) * 2;
    }

    for (int s = 0; s < SS; ++s) {
        float acc[4][4] = {};

        if (s > 0) {
            // h tile (64x512 halves = 4096 uint4, 8 per thread) via cp.async
            const __half* hsrc = g_Hh[s & 1] + (size_t)b0 * HH;
#pragma unroll
            for (int i = 0; i < 8; i++) {
                int id = i * 512 + tid; int row = id >> 6; int c8 = (id & 63) * 8;
                cpasync16(sA32 + (row * 520 + c8) * 2, hsrc + (size_t)row * HH + c8);
            }
            cpasync_wait();
            __syncthreads();

#pragma unroll 4
            for (int kk = 0; kk < HH; kk += 16) {
                uint32_t a[4], b[2][4];
                ldsm4(a, aAddr + kk * 2);
                ldsm4(b[0], bAddr[0] + kk * 2);
                ldsm4(b[1], bAddr[1] + kk * 2);
#pragma unroll
                for (int ni = 0; ni < 4; ni++)
                    mma16816(acc[ni], a, b[ni >> 1] + (ni & 1) * 2);
            }
            __syncthreads();  // done reading sA; stage overwrites it
        }

        // stage acc + XP into smem (transpose to (b, j) ownership)
        const __half* XPb = g_XP + (size_t)s * BB * G4;
#pragma unroll
        for (int ni = 0; ni < 4; ni++) {
            int r = m0w + gq;
            int c = n0w + ni * 8 + t4 * 2;
            float2 x0 = __half22float2(
                *reinterpret_cast<const __half2*>(XPb + (size_t)(b0 + r) * G4 + n0 + c));
            stg[r * 132 + c]     = acc[ni][0] + x0.x;
            stg[r * 132 + c + 1] = acc[ni][1] + x0.y;
            float2 x1 = __half22float2(
                *reinterpret_cast<const __half2*>(XPb + (size_t)(b0 + r + 8) * G4 + n0 + c));
            stg[(r + 8) * 132 + c]     = acc[ni][2] + x1.x;
            stg[(r + 8) * 132 + c + 1] = acc[ni][3] + x1.y;
        }
        __syncthreads();

        // gates: 64 b-rows x 32 j-cols per CTA, 4 per thread
        __half* hdst = g_Hh[(s + 1) & 1];
#pragma unroll
        for (int q = 0; q < 4; q++) {
            int pi = q * 512 + tid;
            int bl = pi >> 5;
            int jl = pi & 31;
            float4 v = *reinterpret_cast<float4*>(stg + bl * 132 + jl * 4);
            float gg = tanhfast(v.x);
            float iv = sigf(v.y);
            float fv = sigf(v.z);
            float ov = sigf(v.w);
            int bg = b0 + bl;
            int jg = nt * 32 + jl;
            float cold = (s == 0) ? 0.f : g_C[(size_t)bg * HH + jg];
            float cnew = gg * iv + cold * fv;
            float hnew = tanhfast(cnew) * ov;
            g_C[(size_t)bg * HH + jg] = cnew;
            hdst[(size_t)bg * HH + jg] = __float2half_rn(hnew);
        }

        // per-group barrier: only the 16 CTAs sharing bt must sync
        ctr_bar(grp_ctr, (unsigned)(s + 1) * 16);
    }

    // one global barrier: projection CTAs read h rows from other groups
    ctr_bar(&g_arrive, NCTA2);

    // final projection: out = h @ Wp^T + bph; final h in g_Hh[0]
    if (cta < 16) {
        const int pb0 = (cta >> 1) * 64;
        const int pn0 = (cta & 1) * 128;
#pragma unroll
        for (int i = 0; i < 16; i++) {
            int id = i * 512 + tid; int row = id >> 6; int c8 = (id & 63) * 8;
            *reinterpret_cast<uint4*>(sW + row * 520 + c8) =
                *reinterpret_cast<const uint4*>(g_Wp_h + (size_t)(pn0 + row) * HH + c8);
        }
#pragma unroll
        for (int i = 0; i < 8; i++) {
            int id = i * 512 + tid; int row = id >> 6; int c8 = (id & 63) * 8;
            *reinterpret_cast<uint4*>(sA + row * 520 + c8) =
                *reinterpret_cast<const uint4*>(g_Hh[0] + (size_t)(pb0 + row) * HH + c8);
        }
        __syncthreads();

        float acc[4][4] = {};
#pragma unroll 4
        for (int kk = 0; kk < HH; kk += 16) {
            uint32_t a[4], b[2][4];
            ldsm4(a, aAddr + kk * 2);
            ldsm4(b[0], bAddr[0] + kk * 2);
            ldsm4(b[1], bAddr[1] + kk * 2);
#pragma unroll
            for (int ni = 0; ni < 4; ni++)
                mma16816(acc[ni], a, b[ni >> 1] + (ni & 1) * 2);
        }
#pragma unroll
        for (int ni = 0; ni < 4; ni++) {
            int r = m0w + gq;
            int c = n0w + ni * 8 + t4 * 2;
            float bv0 = bph[pn0 + c], bv1 = bph[pn0 + c + 1];
            out[(size_t)(pb0 + r) * OO + pn0 + c]     = acc[ni][0] + bv0;
            out[(size_t)(pb0 + r) * OO + pn0 + c + 1] = acc[ni][1] + bv1;
            out[(size_t)(pb0 + r + 8) * OO + pn0 + c]     = acc[ni][2] + bv0;
            out[(size_t)(pb0 + r + 8) * OO + pn0 + c + 1] = acc[ni][3] + bv1;
        }
    }
}

// ---------------- launch ----------------
extern "C" void kernel_launch(void* const* d_in, const int* in_sizes, int n_in,
                              void* d_out, int out_size) {
    (void)in_sizes; (void)n_in; (void)out_size;
    const float* x   = (const float*)d_in[0];
    const float* Wgx = (const float*)d_in[1];
    const float* bgx = (const float*)d_in[2];
    const float* Wgh = (const float*)d_in[3];
    const float* bgh = (const float*)d_in[4];
    const float* Wix = (const float*)d_in[5];
    const float* bix = (const float*)d_in[6];
    const float* Wih = (const float*)d_in[7];
    const float* bih = (const float*)d_in[8];
    const float* Wfx = (const float*)d_in[9];
    const float* bfx = (const float*)d_in[10];
    const float* Wfh = (const float*)d_in[11];
    const float* bfh = (const float*)d_in[12];
    const float* Wox = (const float*)d_in[13];
    const float* box_ = (const float*)d_in[14];
    const float* Woh = (const float*)d_in[15];
    const float* boh = (const float*)d_in[16];
    const float* Wph = (const float*)d_in[17];
    const float* bph = (const float*)d_in[18];

    cudaFuncSetAttribute((const void*)xproj_kernel,
                         cudaFuncAttributeMaxDynamicSharedMemorySize, XPROJ_SMEM);
    cudaFuncSetAttribute((const void*)lstm_kernel,
                         cudaFuncAttributeMaxDynamicSharedMemorySize, LSTM_SMEM);

    pack_kernel<<<(G4 * HH) / PTHREADS, PTHREADS>>>(
        Wgx, Wgh, Wix, Wih, Wfx, Wfh, Wox, Woh,
        bgx, bgh, bix, bih, bfx, bfh, box_, boh, Wph);

    xconv_kernel<<<(BB * SS * II) / (PTHREADS * 8), PTHREADS>>>(x);

    dim3 g1(16, SS * (BB / 64));
    xproj_kernel<<<g1, PTHREADS, XPROJ_SMEM>>>();

    lstm_kernel<<<NCTA2, LTHREADS, LSTM_SMEM>>>(bph, (float*)d_out);
}